// round 15
// baseline (speedup 1.0000x reference)
#include <cuda_runtime.h>
#include <cuda_bf16.h>
#include <math.h>

#define NG 9
#define BMAXE 8192
#define ITILE 1024          // i's per tile = TPB2 * RPT
#define RPT 4               // i's per thread
#define TPB2 256
#define G2 296              // pair-kernel grid (2 blocks/SM on 148 SMs)
#define CHUNKMAX 128        // j's staged in shared per round
#define LOG2E 1.4426950408889634f
#define LN2   0.6931471805599453f

// packed f32x2 FMA: acc += a * b (two lanes)
#define FFMA2(acc, a, bb) asm("fma.rn.f32x2 %0, %1, %2, %0;" : "+l"(acc) : "l"(a), "l"(bb))

// ---------------- device globals (scratch; no dynamic allocation) ----------------
__device__ __align__(16) float    d_lp[BMAXE + ITILE];   // compacted+padded positive (toxic) logits
__device__ __align__(16) unsigned d_mp[BMAXE + ITILE];   // their 9-bit group masks
__device__ __align__(16) float    d_ln[BMAXE];           // compacted negative logits
__device__ __align__(16) unsigned d_mn[BMAXE];           // their masks
__device__ __align__(16) unsigned d_maskAll[BMAXE];
__device__ unsigned d_toxpack[BMAXE / 32];
__device__ int d_nP, d_nN;
__device__ int d_cntSP[NG], d_cntSN[NG];
__device__ __align__(16) float d_partial[27 * G2];       // TRANSPOSED: [lane][block]
__device__ int d_arrive;                                  // zero-init, reset by last block

// ---------------- kernel 1a: masks + toxic bits (coalesced via shared) ----------------
#define MTPB 128
__global__ void __launch_bounds__(MTPB) mask_kernel(const float* __restrict__ ytox,
                                                    const float* __restrict__ yid,
                                                    int B) {
    __shared__ float sY[MTPB * NG];
    const int t = threadIdx.x;
    const int base = blockIdx.x * MTPB;

    // coalesced flat load of the yid tile (MTPB*9 floats)
    const float* src = yid + (size_t)base * NG;
    int tileElems = MTPB * NG;
    int avail = (B - base) * NG; if (avail < 0) avail = 0;
    for (int k = t; k < tileElems; k += MTPB)
        sY[k] = (k < avail) ? src[k] : 0.0f;

    int i = base + t;
    int tox = 0;
    if (i < B) tox = (ytox[i] >= 0.5f) ? 1 : 0;
    __syncthreads();

    unsigned m = 0;
    if (i < B) {
        #pragma unroll
        for (int g = 0; g < NG; g++)
            if (sY[t * NG + g] >= 0.5f) m |= (1u << g);
    }
    d_maskAll[i] = m;
    unsigned bal = __ballot_sync(0xFFFFFFFFu, tox);
    if ((t & 31) == 0) d_toxpack[i >> 5] = bal;
}

// ---------------- kernel 1b: deterministic compaction + counts ----------------
__global__ void __launch_bounds__(1024) compact_kernel(const float* __restrict__ logits, int B) {
    const int t = threadIdx.x;
    const int lane = t & 31;
    const int wid  = t >> 5;
    __shared__ int sW[32];
    __shared__ int sCnt[2 * NG];
    if (t < 2 * NG) sCnt[t] = 0;

    const int E = 8;
    const int base = t * E;

    float lg[8];
    unsigned msk[8];
    if (base + E <= B) {
        float4 a = *(const float4*)&logits[base];
        float4 b = *(const float4*)&logits[base + 4];
        lg[0]=a.x; lg[1]=a.y; lg[2]=a.z; lg[3]=a.w;
        lg[4]=b.x; lg[5]=b.y; lg[6]=b.z; lg[7]=b.w;
        uint4 ma = *(const uint4*)&d_maskAll[base];
        uint4 mb = *(const uint4*)&d_maskAll[base + 4];
        msk[0]=ma.x; msk[1]=ma.y; msk[2]=ma.z; msk[3]=ma.w;
        msk[4]=mb.x; msk[5]=mb.y; msk[6]=mb.z; msk[7]=mb.w;
    } else {
        #pragma unroll
        for (int e = 0; e < E; e++) {
            int i = base + e;
            lg[e]  = (i < B) ? logits[i] : 0.0f;
            msk[e] = (i < B) ? d_maskAll[i] : 0u;
        }
    }
    unsigned toxb = (d_toxpack[t >> 2] >> ((t & 3) * 8)) & 0xFFu;

    // per-group tallies
    int cSP[NG], cSN[NG];
    #pragma unroll
    for (int g = 0; g < NG; g++) { cSP[g] = 0; cSN[g] = 0; }
    int nTox = 0;
    #pragma unroll
    for (int e = 0; e < E; e++) {
        if (base + e >= B) continue;
        int tx = (toxb >> e) & 1u;
        nTox += tx;
        unsigned m = msk[e];
        #pragma unroll
        for (int g = 0; g < NG; g++) {
            if ((m >> g) & 1u) { if (tx) cSP[g]++; else cSN[g]++; }
        }
    }
    __syncthreads();   // sCnt zero visible
    #pragma unroll
    for (int k = 0; k < 2 * NG; k++) {
        int v = (k < NG) ? cSP[k] : cSN[k - NG];
        #pragma unroll
        for (int o = 16; o > 0; o >>= 1) v += __shfl_xor_sync(0xFFFFFFFFu, v, o);
        if (lane == 0) atomicAdd(&sCnt[k], v);
    }

    // block inclusive scan of nTox via warp shuffles (3 barriers total)
    int v = nTox;
    #pragma unroll
    for (int o = 1; o < 32; o <<= 1) {
        int n = __shfl_up_sync(0xFFFFFFFFu, v, o);
        if (lane >= o) v += n;
    }
    if (lane == 31) sW[wid] = v;
    __syncthreads();
    if (wid == 0) {
        int w = sW[lane];
        #pragma unroll
        for (int o = 1; o < 32; o <<= 1) {
            int n = __shfl_up_sync(0xFFFFFFFFu, w, o);
            if (lane >= o) w += n;
        }
        sW[lane] = w;
    }
    __syncthreads();
    int incl = v + ((wid > 0) ? sW[wid - 1] : 0);
    int totTox = sW[31];
    int posIdx = incl - nTox;
    int negIdx = base - (incl - nTox);

    #pragma unroll
    for (int e = 0; e < E; e++) {
        int i = base + e;
        if (i >= B) continue;
        if ((toxb >> e) & 1u) {
            d_lp[posIdx] = lg[e]; d_mp[posIdx] = msk[e]; posIdx++;
        } else {
            d_ln[negIdx] = lg[e]; d_mn[negIdx] = msk[e]; negIdx++;
        }
    }

    int nP = totTox;
    int nTileI = (nP + ITILE - 1) / ITILE; if (nTileI < 1) nTileI = 1;
    int nPpad = nTileI * ITILE;
    // pad positives with sentinel so softplus contribution is exactly 0
    for (int k = nP + t; k < nPpad; k += 1024) { d_lp[k] = 1e30f; d_mp[k] = 0u; }

    if (t == 0) { d_nP = nP; d_nN = B - nP; }
    __syncthreads();
    if (t < NG)               d_cntSP[t] = sCnt[t];
    if (t >= NG && t < 2*NG)  d_cntSN[t - NG] = sCnt[t];
}

// ---------------- kernel 2: pair accumulation + folded finalize ----------------
__global__ void __launch_bounds__(TPB2) pair_kernel(float* __restrict__ out) {
    const int nP = d_nP;
    const int nN = d_nN;
    const int b = blockIdx.x;
    const int t = threadIdx.x;

    __shared__ float  sLj[CHUNKMAX];          // lj * log2(e)
    __shared__ float2 sM[CHUNKMAX][6];        // 5 mask pairs/row (lane4.y = 1.0 -> rowsum) + pad
    __shared__ float  sPart[TPB2 * 29];       // per-thread 27 partials, stride 29
    __shared__ float  sQ[27][8];
    __shared__ float  accF[27];
    __shared__ int    sLast;

    int nTileI = (nP + ITILE - 1) / ITILE; if (nTileI < 1) nTileI = 1;
    int it  = b % nTileI;
    int idx = b / nTileI;
    int nB  = (G2 + nTileI - 1 - it) / nTileI;   // blocks sharing this i-tile
    int j0  = (int)((long long)idx * nN / nB);
    int j1  = (int)((long long)(idx + 1) * nN / nB);
    if (j0 > j1) j1 = j0;

    // my RPT i's (padded region: li=1e30 sentinel -> s==0; mask==0)
    float li2[RPT]; unsigned mi[RPT];
    int ib = it * ITILE + t;
    #pragma unroll
    for (int r = 0; r < RPT; r++) {
        li2[r] = d_lp[ib + r * TPB2] * LOG2E;
        mi[r]  = d_mp[ib + r * TPB2];
    }

    unsigned long long H2[RPT][5];   // packed f32x2: groups (0,1)(2,3)(4,5)(6,7)(8,rowsum)
    #pragma unroll
    for (int r = 0; r < RPT; r++)
        #pragma unroll
        for (int g = 0; g < 5; g++) H2[r][g] = 0ull;

    for (int jc = j0; jc < j1; jc += CHUNKMAX) {
        int jcnt = j1 - jc; if (jcnt > CHUNKMAX) jcnt = CHUNKMAX;
        __syncthreads();
        for (int j = t; j < jcnt; j += TPB2) {
            sLj[j] = d_ln[jc + j] * LOG2E;
            unsigned m = d_mn[jc + j];
            #pragma unroll
            for (int g = 0; g < 5; g++) {
                float x = (float)((m >> (2 * g)) & 1u);
                float y = (g < 4) ? (float)((m >> (2 * g + 1)) & 1u) : 1.0f;  // lane 9 = rowsum
                sM[j][g] = make_float2(x, y);
            }
        }
        __syncthreads();

        for (int j = 0; j < jcnt; j++) {
            const float lj2 = sLj[j];
            const unsigned long long* qp = (const unsigned long long*)&sM[j][0];
            const unsigned long long q0 = qp[0], q1 = qp[1], q2 = qp[2], q3 = qp[3], q4 = qp[4];
            #pragma unroll
            for (int r = 0; r < RPT; r++) {
                // softplus in log2 domain: s2 = lg2(1 + 2^(lj2 - li2)); true s = s2*ln2 (applied at end)
                float d2 = lj2 - li2[r];
                float e;  asm("ex2.approx.ftz.f32 %0, %1;" : "=f"(e) : "f"(d2));
                float u = 1.0f + e;
                float s2; asm("lg2.approx.ftz.f32 %0, %1;" : "=f"(s2) : "f"(u));
                unsigned long long sp;
                asm("mov.b64 %0, {%1, %1};" : "=l"(sp) : "r"(__float_as_uint(s2)));
                FFMA2(H2[r][0], sp, q0);
                FFMA2(H2[r][1], sp, q1);
                FFMA2(H2[r][2], sp, q2);
                FFMA2(H2[r][3], sp, q3);
                FFMA2(H2[r][4], sp, q4);   // lane .y accumulates rowsum (Gr)
            }
        }
    }

    // per-thread partials: both (mi&mj), jin (mj only), iin (mi only) -- in log2 units
    {
        float p[27];
        #pragma unroll
        for (int k = 0; k < 27; k++) p[k] = 0.0f;
        #pragma unroll
        for (int r = 0; r < RPT; r++) {
            float Hf[10];
            #pragma unroll
            for (int g = 0; g < 5; g++) {
                uint2 u = *(uint2*)&H2[r][g];
                Hf[2 * g]     = __uint_as_float(u.x);
                Hf[2 * g + 1] = __uint_as_float(u.y);
            }
            float Gr = Hf[9];
            #pragma unroll
            for (int g = 0; g < NG; g++) {
                p[NG + g] += Hf[g];                                    // jin
                if ((mi[r] >> g) & 1u) { p[g] += Hf[g]; p[2*NG + g] += Gr; }  // both, iin
            }
        }
        // conflict-free store: bank = (29t + k) mod 32, distinct t -> distinct banks
        #pragma unroll
        for (int k = 0; k < 27; k++) sPart[t * 29 + k] = p[k];
    }
    __syncthreads();

    // 216 threads reduce the 27 columns over 256 rows (skewed, bank-conflict-free)
    if (t < 216) {
        int k  = t >> 3;        // 0..26
        int p8 = t & 7;         // 0..7: row slice [p8*32, p8*32+32)
        float s = 0.0f;
        #pragma unroll
        for (int m = 0; m < 32; m++) {
            int mm = (m + 4 * p8) & 31;
            s += sPart[(p8 * 32 + mm) * 29 + k];
        }
        sQ[k][p8] = s;
    }
    __syncthreads();
    if (t < 27) {
        float v = 0.0f;
        #pragma unroll
        for (int p = 0; p < 8; p++) v += sQ[t][p];
        d_partial[t * G2 + b] = v;   // transposed for coalesced final reduce
    }

    // ---- last-block finalize (deterministic: fixed reduction order, any block) ----
    __threadfence();
    __syncthreads();
    if (t == 0) {
        int old = atomicAdd(&d_arrive, 1);
        __threadfence();
        sLast = (old == G2 - 1) ? 1 : 0;
    }
    __syncthreads();
    if (sLast) {
        int wid = t >> 5, lane = t & 31;
        for (int k = wid; k < 27; k += 8) {
            float s = 0.0f;
            for (int bb = lane; bb < G2; bb += 32) s += d_partial[k * G2 + bb];
            #pragma unroll
            for (int o = 16; o > 0; o >>= 1) s += __shfl_xor_sync(0xFFFFFFFFu, s, o);
            if (lane == 0) accF[k] = s * LN2;   // log2 units -> nat units
        }
        __syncthreads();
        if (t == 0) {
            float fnP = (float)nP, fnN = (float)nN;
            float sum4 = 0.0f, sgv = 0.0f;
            #pragma unroll
            for (int g = 0; g < NG; g++) {
                float SP = (float)d_cntSP[g], SN = (float)d_cntSN[g];
                float BP = fnP - SP, BN = fnN - SN;
                float both = accF[g], jin = accF[NG + g], iin = accF[2 * NG + g];
                float num0 = both, num1 = jin - both, num2 = iin - both;
                float cnt0 = SP * SN, cnt1 = BP * SN, cnt2 = SP * BN;   // exact in fp32
                float nv = 0.0f, accl = 0.0f;
                if (cnt0 > 0.0f) { nv += 1.0f; accl += num0 / fmaxf(cnt0, 1.0f); }
                if (cnt1 > 0.0f) { nv += 1.0f; accl += num1 / fmaxf(cnt1, 1.0f); }
                if (cnt2 > 0.0f) { nv += 1.0f; accl += num2 / fmaxf(cnt2, 1.0f); }
                float gl = accl / fmaxf(nv, 1.0f);
                float gv = (nv > 0.0f) ? 1.0f : 0.0f;
                sgv += gv;
                float gl2 = gl * gl;
                sum4 += gl2 * gl2 * gv;
            }
            float meanp = sum4 / fmaxf(sgv, 1.0f);
            float loss  = sqrtf(sqrtf(meanp));       // meanp^(1/4)
            out[0] = (sgv > 0.0f) ? loss : 0.0f;
            d_arrive = 0;                             // reset for next graph replay
        }
    }
}

// ---------------- launch ----------------
extern "C" void kernel_launch(void* const* d_in, const int* in_sizes, int n_in,
                              void* d_out, int out_size) {
    const float* logits = (const float*)d_in[0];
    const float* ytox   = (const float*)d_in[1];
    const float* yid    = (const float*)d_in[2];
    int B = in_sizes[0];
    if (B > BMAXE) B = BMAXE;

    mask_kernel<<<BMAXE / MTPB, MTPB>>>(ytox, yid, B);
    compact_kernel<<<1, 1024>>>(logits, B);
    pair_kernel<<<G2, TPB2>>>((float*)d_out);
}

// round 16
// speedup vs baseline: 1.4528x; 1.4528x over previous
#include <cuda_runtime.h>
#include <cuda_bf16.h>
#include <math.h>

#define NG 9
#define BMAXE 8192
#define ITILE 1024          // i's per tile = TPB2 * RPT
#define RPT 4               // i's per thread
#define TPB2 256
#define G2 296              // grid: 148 SMs x 2 co-resident blocks
#define SLICEBLKS 256       // blocks that own a 32-element input slice
#define CHUNKMAX 128        // j's staged in shared per round
#define LOG2E 1.4426950408889634f
#define LN2   0.6931471805599453f

// packed f32x2 FMA: acc += a * b (two lanes)
#define FFMA2(acc, a, bb) asm("fma.rn.f32x2 %0, %1, %2, %0;" : "+l"(acc) : "l"(a), "l"(bb))

// ---------------- device globals (scratch; zero-init once; reset in-kernel) ----------------
__device__ __align__(16) float    d_lp[BMAXE + ITILE];
__device__ __align__(16) unsigned d_mp[BMAXE + ITILE];
__device__ __align__(16) float    d_ln[BMAXE];
__device__ __align__(16) unsigned d_mn[BMAXE];
__device__ int d_blkTox[SLICEBLKS];
__device__ int d_cntSP[NG], d_cntSN[NG];
__device__ __align__(16) float d_partial[27 * G2];   // TRANSPOSED: [lane][block]
__device__ int d_barCnt[3];                          // grid barrier counters (reset by block 0)
__device__ int d_barFlag[3];

// grid-wide barrier: all G2 blocks co-resident (2/SM), deterministic
__device__ __forceinline__ void gridBarrier(int id) {
    __syncthreads();
    if (threadIdx.x == 0) {
        __threadfence();
        volatile int* flag = &d_barFlag[id];
        if (atomicAdd(&d_barCnt[id], 1) == G2 - 1) {
            *flag = 1;
        } else {
            while (*flag == 0) { }
        }
        __threadfence();
    }
    __syncthreads();
}

__global__ void __launch_bounds__(TPB2, 2)
fused_kernel(const float* __restrict__ logits,
             const float* __restrict__ ytox,
             const float* __restrict__ yid,
             float* __restrict__ out, int B) {
    const int b    = blockIdx.x;
    const int t    = threadIdx.x;
    const int lane = t & 31;
    const int wid  = t >> 5;

    // ---- shared ----
    __shared__ int   sTox[SLICEBLKS];
    __shared__ int   sW[8], sP[8], sBc[2];
    __shared__ float  sLj[CHUNKMAX];
    __shared__ float2 sM[CHUNKMAX][6];
    __shared__ float  sPart[TPB2 * 29];
    __shared__ float  sQ[27][8];
    __shared__ float  accF[27];

    // ================= Phase A: masks + tox + counts (warp 0 of blocks < 256) =================
    float    myLg = 0.0f;
    unsigned myMask = 0u;
    int      myTox = 0, myValid = 0;
    unsigned balTox = 0u;
    if (b < SLICEBLKS && wid == 0) {
        int i = b * 32 + lane;
        if (i < B) {
            myValid = 1;
            myLg  = logits[i];
            myTox = (ytox[i] >= 0.5f) ? 1 : 0;
            const float* row = yid + (size_t)i * NG;
            #pragma unroll
            for (int g = 0; g < NG; g++)
                if (row[g] >= 0.5f) myMask |= (1u << g);
        }
        balTox = __ballot_sync(0xFFFFFFFFu, myTox);
        unsigned bgAll[NG];
        #pragma unroll
        for (int g = 0; g < NG; g++)
            bgAll[g] = __ballot_sync(0xFFFFFFFFu, (myMask >> g) & 1u);
        int myCnt = 0;
        #pragma unroll
        for (int g = 0; g < NG; g++) {
            if (lane == g)      myCnt = __popc(bgAll[g] & balTox);    // SP
            if (lane == NG + g) myCnt = __popc(bgAll[g] & ~balTox);   // SN (bg subset of valid)
        }
        if (lane < NG)            atomicAdd(&d_cntSP[lane], myCnt);
        else if (lane < 2 * NG)   atomicAdd(&d_cntSN[lane - NG], myCnt);
        if (lane == 0) d_blkTox[b] = __popc(balTox);
    }
    gridBarrier(0);

    // ================= Phase B: prefix + scatter + pad =================
    if (t < SLICEBLKS) sTox[t] = d_blkTox[t];
    __syncthreads();
    {
        int x   = (t < SLICEBLKS) ? sTox[t] : 0;
        int pre = (t < b) ? x : 0;                  // toxic count in blocks before mine
        #pragma unroll
        for (int o = 16; o > 0; o >>= 1) {
            x   += __shfl_xor_sync(0xFFFFFFFFu, x, o);
            pre += __shfl_xor_sync(0xFFFFFFFFu, pre, o);
        }
        if (lane == 0) { sW[wid] = x; sP[wid] = pre; }
    }
    __syncthreads();
    if (t == 0) {
        int X = 0, P = 0;
        #pragma unroll
        for (int w = 0; w < 8; w++) { X += sW[w]; P += sP[w]; }
        sBc[0] = X; sBc[1] = P;
    }
    __syncthreads();
    const int nP    = sBc[0];
    const int myPre = sBc[1];
    const int nN    = B - nP;

    if (b < SLICEBLKS && wid == 0 && myValid) {
        int toxBefore = __popc(balTox & ((1u << lane) - 1u));
        int i = b * 32 + lane;
        if (myTox) {
            int p = myPre + toxBefore;
            d_lp[p] = myLg; d_mp[p] = myMask;
        } else {
            int p = i - myPre - toxBefore;
            d_ln[p] = myLg; d_mn[p] = myMask;
        }
    }
    int nTileI = (nP + ITILE - 1) / ITILE; if (nTileI < 1) nTileI = 1;
    const int nPpad = nTileI * ITILE;
    {
        int k = b * TPB2 + t;
        if (k < nPpad - nP) { d_lp[nP + k] = 1e30f; d_mp[nP + k] = 0u; }  // sentinel: s == 0
    }
    gridBarrier(1);

    // ================= Phase C: pair accumulation =================
    int it  = b % nTileI;
    int idx = b / nTileI;
    int nB  = (G2 + nTileI - 1 - it) / nTileI;
    int j0  = (int)((long long)idx * nN / nB);
    int j1  = (int)((long long)(idx + 1) * nN / nB);
    if (j0 > j1) j1 = j0;

    float li2[RPT]; unsigned mi[RPT];
    int ib = it * ITILE + t;
    #pragma unroll
    for (int r = 0; r < RPT; r++) {
        li2[r] = d_lp[ib + r * TPB2] * LOG2E;
        mi[r]  = d_mp[ib + r * TPB2];
    }

    unsigned long long H2[RPT][5];   // packed f32x2: groups (0,1)(2,3)(4,5)(6,7)(8,rowsum)
    #pragma unroll
    for (int r = 0; r < RPT; r++)
        #pragma unroll
        for (int g = 0; g < 5; g++) H2[r][g] = 0ull;

    for (int jc = j0; jc < j1; jc += CHUNKMAX) {
        int jcnt = j1 - jc; if (jcnt > CHUNKMAX) jcnt = CHUNKMAX;
        __syncthreads();
        for (int j = t; j < jcnt; j += TPB2) {
            sLj[j] = d_ln[jc + j] * LOG2E;
            unsigned m = d_mn[jc + j];
            #pragma unroll
            for (int g = 0; g < 5; g++) {
                float x = (float)((m >> (2 * g)) & 1u);
                float y = (g < 4) ? (float)((m >> (2 * g + 1)) & 1u) : 1.0f;  // lane 9 = rowsum
                sM[j][g] = make_float2(x, y);
            }
        }
        __syncthreads();

        for (int j = 0; j < jcnt; j++) {
            const float lj2 = sLj[j];
            const unsigned long long* qp = (const unsigned long long*)&sM[j][0];
            const unsigned long long q0 = qp[0], q1 = qp[1], q2 = qp[2], q3 = qp[3], q4 = qp[4];
            #pragma unroll
            for (int r = 0; r < RPT; r++) {
                // softplus in log2 domain: s2 = lg2(1 + 2^(lj2-li2)); s = s2*ln2 applied at end
                float d2 = lj2 - li2[r];
                float e;  asm("ex2.approx.ftz.f32 %0, %1;" : "=f"(e) : "f"(d2));
                float u = 1.0f + e;
                float s2; asm("lg2.approx.ftz.f32 %0, %1;" : "=f"(s2) : "f"(u));
                unsigned long long sp;
                asm("mov.b64 %0, {%1, %1};" : "=l"(sp) : "r"(__float_as_uint(s2)));
                FFMA2(H2[r][0], sp, q0);
                FFMA2(H2[r][1], sp, q1);
                FFMA2(H2[r][2], sp, q2);
                FFMA2(H2[r][3], sp, q3);
                FFMA2(H2[r][4], sp, q4);   // .y accumulates rowsum (Gr)
            }
        }
    }

    // per-thread partials: both / jin / iin (log2 units)
    {
        float p[27];
        #pragma unroll
        for (int k = 0; k < 27; k++) p[k] = 0.0f;
        #pragma unroll
        for (int r = 0; r < RPT; r++) {
            float Hf[10];
            #pragma unroll
            for (int g = 0; g < 5; g++) {
                uint2 u = *(uint2*)&H2[r][g];
                Hf[2 * g]     = __uint_as_float(u.x);
                Hf[2 * g + 1] = __uint_as_float(u.y);
            }
            float Gr = Hf[9];
            #pragma unroll
            for (int g = 0; g < NG; g++) {
                p[NG + g] += Hf[g];
                if ((mi[r] >> g) & 1u) { p[g] += Hf[g]; p[2 * NG + g] += Gr; }
            }
        }
        #pragma unroll
        for (int k = 0; k < 27; k++) sPart[t * 29 + k] = p[k];
    }
    __syncthreads();

    if (t < 216) {
        int k  = t >> 3;
        int p8 = t & 7;
        float s = 0.0f;
        #pragma unroll
        for (int m = 0; m < 32; m++) {
            int mm = (m + 4 * p8) & 31;
            s += sPart[(p8 * 32 + mm) * 29 + k];
        }
        sQ[k][p8] = s;
    }
    __syncthreads();
    if (t < 27) {
        float v = 0.0f;
        #pragma unroll
        for (int p = 0; p < 8; p++) v += sQ[t][p];
        d_partial[t * G2 + b] = v;
    }

    // ================= finalize: block 0, fixed order =================
    gridBarrier(2);
    if (b == 0) {
        for (int k = wid; k < 27; k += 8) {
            float s = 0.0f;
            for (int bb = lane; bb < G2; bb += 32) s += d_partial[k * G2 + bb];
            #pragma unroll
            for (int o = 16; o > 0; o >>= 1) s += __shfl_xor_sync(0xFFFFFFFFu, s, o);
            if (lane == 0) accF[k] = s * LN2;   // log2 -> nat units
        }
        __syncthreads();
        if (t == 0) {
            float fnP = (float)nP, fnN = (float)nN;
            float sum4 = 0.0f, sgv = 0.0f;
            #pragma unroll
            for (int g = 0; g < NG; g++) {
                float SP = (float)d_cntSP[g], SN = (float)d_cntSN[g];
                float BP = fnP - SP, BN = fnN - SN;
                float both = accF[g], jin = accF[NG + g], iin = accF[2 * NG + g];
                float num0 = both, num1 = jin - both, num2 = iin - both;
                float cnt0 = SP * SN, cnt1 = BP * SN, cnt2 = SP * BN;   // exact in fp32
                float nv = 0.0f, accl = 0.0f;
                if (cnt0 > 0.0f) { nv += 1.0f; accl += num0 / fmaxf(cnt0, 1.0f); }
                if (cnt1 > 0.0f) { nv += 1.0f; accl += num1 / fmaxf(cnt1, 1.0f); }
                if (cnt2 > 0.0f) { nv += 1.0f; accl += num2 / fmaxf(cnt2, 1.0f); }
                float gl = accl / fmaxf(nv, 1.0f);
                float gv = (nv > 0.0f) ? 1.0f : 0.0f;
                sgv += gv;
                float gl2 = gl * gl;
                sum4 += gl2 * gl2 * gv;
            }
            float meanp = sum4 / fmaxf(sgv, 1.0f);
            float loss  = sqrtf(sqrtf(meanp));
            out[0] = (sgv > 0.0f) ? loss : 0.0f;
            // reset all cross-replay state (graph replays must be identical)
            #pragma unroll
            for (int g = 0; g < NG; g++) { d_cntSP[g] = 0; d_cntSN[g] = 0; }
            d_barCnt[0] = 0; d_barCnt[1] = 0; d_barCnt[2] = 0;
            d_barFlag[0] = 0; d_barFlag[1] = 0; d_barFlag[2] = 0;
            __threadfence();
        }
    }
}

// ---------------- launch ----------------
extern "C" void kernel_launch(void* const* d_in, const int* in_sizes, int n_in,
                              void* d_out, int out_size) {
    const float* logits = (const float*)d_in[0];
    const float* ytox   = (const float*)d_in[1];
    const float* yid    = (const float*)d_in[2];
    int B = in_sizes[0];
    if (B > BMAXE) B = BMAXE;

    fused_kernel<<<G2, TPB2>>>(logits, ytox, yid, (float*)d_out, B);
}